// round 2
// baseline (speedup 1.0000x reference)
#include <cuda_runtime.h>

#define NUM_NODES 50000
#define INPUT_SIZE 128
#define NUM_REL 16
#define NUM_EDGES 1600000
#define CLAMP_MIN 1e-5f
#define CLAMP_MAX 0.99999f

// Node logit table: T[n][0:16] = x[n] . W[0:128, :], T[n][16:32] = x[n] . W[128:256, :]
__device__ float g_table[NUM_NODES * 32];

// ---------------------------------------------------------------------------
// Kernel A: 50000x128 @ 128x32 GEMM into g_table.
// Block: 256 threads, tile 128 nodes x 32 rel-cols. Each thread: 4 nodes x 4 cols.
// ---------------------------------------------------------------------------
__global__ void __launch_bounds__(256) node_logits_kernel(
    const float* __restrict__ x, const float* __restrict__ W)
{
    __shared__ float Ws[INPUT_SIZE][32];   // Ws[k][r]  (16 KB)
    __shared__ float Xs[32][129];          // Xs[k][n], 32 k-slices x 128 nodes (+pad)

    const int tid = threadIdx.x;

    // Stage W once: combined [128][32] layout (src cols 0..15, dst cols 16..31)
    for (int idx = tid; idx < INPUT_SIZE * 32; idx += 256) {
        int k = idx >> 5;
        int r = idx & 31;
        Ws[k][r] = (r < NUM_REL) ? W[k * NUM_REL + r]
                                 : W[(k + INPUT_SIZE) * NUM_REL + (r - NUM_REL)];
    }

    const int node0 = blockIdx.x * 128;
    const int rg = tid & 7;    // 8 groups of 4 rel-cols
    const int ng = tid >> 3;   // 32 groups of 4 nodes

    float acc[4][4];
#pragma unroll
    for (int i = 0; i < 4; ++i)
#pragma unroll
        for (int j = 0; j < 4; ++j) acc[i][j] = 0.0f;

    for (int kc = 0; kc < 4; ++kc) {
        __syncthreads();
#pragma unroll
        for (int it = 0; it < 4; ++it) {
            int s = tid + it * 256;      // 0..1023
            int row = s >> 3;            // 0..127 (node within tile)
            int c4  = s & 7;             // which float4 of the 32-float k-chunk
            int gr = node0 + row;
            if (gr >= NUM_NODES) gr = NUM_NODES - 1;   // safe clamp (dup loads OK)
            float4 v = *reinterpret_cast<const float4*>(
                &x[(size_t)gr * INPUT_SIZE + kc * 32 + c4 * 4]);
            Xs[c4 * 4 + 0][row] = v.x;
            Xs[c4 * 4 + 1][row] = v.y;
            Xs[c4 * 4 + 2][row] = v.z;
            Xs[c4 * 4 + 3][row] = v.w;
        }
        __syncthreads();

#pragma unroll
        for (int kk = 0; kk < 32; ++kk) {
            int k = kc * 32 + kk;
            float4 wv = *reinterpret_cast<const float4*>(&Ws[k][rg * 4]);
            float xa0 = Xs[kk][ng * 4 + 0];
            float xa1 = Xs[kk][ng * 4 + 1];
            float xa2 = Xs[kk][ng * 4 + 2];
            float xa3 = Xs[kk][ng * 4 + 3];
            acc[0][0] += xa0 * wv.x; acc[0][1] += xa0 * wv.y;
            acc[0][2] += xa0 * wv.z; acc[0][3] += xa0 * wv.w;
            acc[1][0] += xa1 * wv.x; acc[1][1] += xa1 * wv.y;
            acc[1][2] += xa1 * wv.z; acc[1][3] += xa1 * wv.w;
            acc[2][0] += xa2 * wv.x; acc[2][1] += xa2 * wv.y;
            acc[2][2] += xa2 * wv.z; acc[2][3] += xa2 * wv.w;
            acc[3][0] += xa3 * wv.x; acc[3][1] += xa3 * wv.y;
            acc[3][2] += xa3 * wv.z; acc[3][3] += xa3 * wv.w;
        }
    }

#pragma unroll
    for (int i = 0; i < 4; ++i) {
        int n = node0 + ng * 4 + i;
        if (n < NUM_NODES) {
            float4 o = make_float4(acc[i][0], acc[i][1], acc[i][2], acc[i][3]);
            *reinterpret_cast<float4*>(&g_table[(size_t)n * 32 + rg * 4]) = o;
        }
    }
}

// ---------------------------------------------------------------------------
// Kernel B: per-edge gather + sigmoid + clamp.
// int32 indices (JAX demotes int64->int32 without x64). 4 consecutive edges
// per thread via int4/float4 for fully coalesced 16B accesses.
// ---------------------------------------------------------------------------
__device__ __forceinline__ float edge_prob(int s, int d, int t)
{
    // Defensive clamps: guarantee in-bounds even if dtype assumption is wrong.
    s = min(max(s, 0), NUM_NODES - 1);
    d = min(max(d, 0), NUM_NODES - 1);
    t = t & 15;
    float a = g_table[s * 32 + t] + g_table[d * 32 + 16 + t];
    float p = 1.0f / (1.0f + __expf(-a));
    return fminf(fmaxf(p, CLAMP_MIN), CLAMP_MAX);
}

__global__ void __launch_bounds__(256) edge_kernel(
    const int* __restrict__ ei,
    const int* __restrict__ et,
    float* __restrict__ out)
{
    const int q = blockIdx.x * 256 + threadIdx.x;   // quad index
    const int e0 = q * 4;
    if (e0 + 3 < NUM_EDGES) {
        int4 s4 = *reinterpret_cast<const int4*>(ei + e0);
        int4 d4 = *reinterpret_cast<const int4*>(ei + NUM_EDGES + e0);
        int4 t4 = *reinterpret_cast<const int4*>(et + e0);
        float4 o;
        o.x = edge_prob(s4.x, d4.x, t4.x);
        o.y = edge_prob(s4.y, d4.y, t4.y);
        o.z = edge_prob(s4.z, d4.z, t4.z);
        o.w = edge_prob(s4.w, d4.w, t4.w);
        *reinterpret_cast<float4*>(out + e0) = o;
    } else {
        for (int e = e0; e < NUM_EDGES; ++e)
            out[e] = edge_prob(ei[e], ei[NUM_EDGES + e], et[e]);
    }
}

extern "C" void kernel_launch(void* const* d_in, const int* in_sizes, int n_in,
                              void* d_out, int out_size)
{
    const float* x  = (const float*)d_in[0];
    const float* W  = (const float*)d_in[1];
    const int*   ei = (const int*)d_in[2];
    const int*   et = (const int*)d_in[3];
    float* out = (float*)d_out;

    const int node_blocks = (NUM_NODES + 127) / 128;            // 391
    node_logits_kernel<<<node_blocks, 256>>>(x, W);

    const int quads = (NUM_EDGES + 3) / 4;                      // 400000
    const int edge_blocks = (quads + 255) / 256;                // 1563
    edge_kernel<<<edge_blocks, 256>>>(ei, et, out);
}

// round 3
// speedup vs baseline: 1.0104x; 1.0104x over previous
#include <cuda_runtime.h>

#define NUM_NODES 50000
#define INPUT_SIZE 128
#define NUM_REL 16
#define NUM_EDGES 1600000
#define CLAMP_MIN 1e-5f
#define CLAMP_MAX 0.99999f

// Node logit table: T[n][0:16] = x[n].W_src, T[n][16:32] = x[n].W_dst
__device__ float g_table[NUM_NODES * 32];

// ---------------------------------------------------------------------------
// Kernel A: 50000x128 @ 128x32 GEMM into g_table.
// 128 threads/block, tile 128 nodes x 32 cols. Per thread: 8 nodes x 4 cols.
// Per kk: 2x LDS.128 (Xs) + 1x LDS.128 (Ws) + 32 FFMA  -> 96 B/cyc LDS demand
// at peak FFMA rate (under the 128 B/cyc crossbar).
// ---------------------------------------------------------------------------
#define XPAD 132   // Xs row stride (floats): 16B-aligned float4s, conflict-free reads

__global__ void __launch_bounds__(128) node_logits_kernel(
    const float* __restrict__ x, const float* __restrict__ W)
{
    __shared__ float Ws[INPUT_SIZE][32];     // 16 KB, [k][r]
    __shared__ float Xs[32][XPAD];           // 16.9 KB, [k][node]

    const int tid = threadIdx.x;

    // Stage W: combined [128][32] (src cols 0..15, dst cols 16..31)
    for (int idx = tid; idx < INPUT_SIZE * 32; idx += 128) {
        int k = idx >> 5;
        int r = idx & 31;
        Ws[k][r] = (r < NUM_REL) ? W[k * NUM_REL + r]
                                 : W[(k + INPUT_SIZE) * NUM_REL + (r - NUM_REL)];
    }

    const int node0 = blockIdx.x * 128;
    const int rg = tid & 7;    // 8 groups of 4 rel-cols
    const int ng = tid >> 3;   // 16 groups of 8 nodes

    float acc[8][4];
#pragma unroll
    for (int i = 0; i < 8; ++i)
#pragma unroll
        for (int j = 0; j < 4; ++j) acc[i][j] = 0.0f;

    for (int kc = 0; kc < 4; ++kc) {
        __syncthreads();
        // Load x[node0..node0+127][kc*32..+32] transposed into Xs[k][node]
#pragma unroll
        for (int it = 0; it < 8; ++it) {
            int s = tid + it * 128;      // 0..1023
            int row = s >> 3;            // node within tile 0..127
            int c4  = s & 7;             // float4 within the 32-float k-chunk
            int gr = node0 + row;
            if (gr >= NUM_NODES) gr = NUM_NODES - 1;   // dup loads OK
            float4 v = *reinterpret_cast<const float4*>(
                &x[(size_t)gr * INPUT_SIZE + kc * 32 + c4 * 4]);
            Xs[c4 * 4 + 0][row] = v.x;
            Xs[c4 * 4 + 1][row] = v.y;
            Xs[c4 * 4 + 2][row] = v.z;
            Xs[c4 * 4 + 3][row] = v.w;
        }
        __syncthreads();

#pragma unroll
        for (int kk = 0; kk < 32; ++kk) {
            int k = kc * 32 + kk;
            float4 wv = *reinterpret_cast<const float4*>(&Ws[k][rg * 4]);
            float4 xa = *reinterpret_cast<const float4*>(&Xs[kk][ng * 8]);
            float4 xb = *reinterpret_cast<const float4*>(&Xs[kk][ng * 8 + 4]);
            float xr[8] = {xa.x, xa.y, xa.z, xa.w, xb.x, xb.y, xb.z, xb.w};
#pragma unroll
            for (int i = 0; i < 8; ++i) {
                acc[i][0] += xr[i] * wv.x;
                acc[i][1] += xr[i] * wv.y;
                acc[i][2] += xr[i] * wv.z;
                acc[i][3] += xr[i] * wv.w;
            }
        }
    }

#pragma unroll
    for (int i = 0; i < 8; ++i) {
        int n = node0 + ng * 8 + i;
        if (n < NUM_NODES) {
            float4 o = make_float4(acc[i][0], acc[i][1], acc[i][2], acc[i][3]);
            *reinterpret_cast<float4*>(&g_table[(size_t)n * 32 + rg * 4]) = o;
        }
    }
}

// ---------------------------------------------------------------------------
// Kernel B: per-edge gather + sigmoid + clamp. 8 edges/thread, all 16 gathers
// issued back-to-back (MLP=16) before any consumption.
// ---------------------------------------------------------------------------
__global__ void __launch_bounds__(256) edge_kernel(
    const int* __restrict__ ei,
    const int* __restrict__ et,
    float* __restrict__ out)
{
    const int e0 = (blockIdx.x * 256 + threadIdx.x) * 8;
    if (e0 + 7 < NUM_EDGES) {
        int4 s4a = *reinterpret_cast<const int4*>(ei + e0);
        int4 s4b = *reinterpret_cast<const int4*>(ei + e0 + 4);
        int4 d4a = *reinterpret_cast<const int4*>(ei + NUM_EDGES + e0);
        int4 d4b = *reinterpret_cast<const int4*>(ei + NUM_EDGES + e0 + 4);
        int4 t4a = *reinterpret_cast<const int4*>(et + e0);
        int4 t4b = *reinterpret_cast<const int4*>(et + e0 + 4);

        int s[8] = {s4a.x, s4a.y, s4a.z, s4a.w, s4b.x, s4b.y, s4b.z, s4b.w};
        int d[8] = {d4a.x, d4a.y, d4a.z, d4a.w, d4b.x, d4b.y, d4b.z, d4b.w};
        int t[8] = {t4a.x, t4a.y, t4a.z, t4a.w, t4b.x, t4b.y, t4b.z, t4b.w};

        float a[8], b[8];
#pragma unroll
        for (int i = 0; i < 8; ++i) a[i] = __ldg(&g_table[s[i] * 32 + t[i]]);
#pragma unroll
        for (int i = 0; i < 8; ++i) b[i] = __ldg(&g_table[d[i] * 32 + 16 + t[i]]);

        float o[8];
#pragma unroll
        for (int i = 0; i < 8; ++i) {
            float p = 1.0f / (1.0f + __expf(-(a[i] + b[i])));
            o[i] = fminf(fmaxf(p, CLAMP_MIN), CLAMP_MAX);
        }
        *reinterpret_cast<float4*>(out + e0)     = make_float4(o[0], o[1], o[2], o[3]);
        *reinterpret_cast<float4*>(out + e0 + 4) = make_float4(o[4], o[5], o[6], o[7]);
    } else {
        for (int e = e0; e < NUM_EDGES; ++e) {
            int s = ei[e], d = ei[NUM_EDGES + e], t = et[e];
            float p = 1.0f / (1.0f + __expf(-(g_table[s * 32 + t] + g_table[d * 32 + 16 + t])));
            out[e] = fminf(fmaxf(p, CLAMP_MIN), CLAMP_MAX);
        }
    }
}

extern "C" void kernel_launch(void* const* d_in, const int* in_sizes, int n_in,
                              void* d_out, int out_size)
{
    const float* x  = (const float*)d_in[0];
    const float* W  = (const float*)d_in[1];
    const int*   ei = (const int*)d_in[2];
    const int*   et = (const int*)d_in[3];
    float* out = (float*)d_out;

    const int node_blocks = (NUM_NODES + 127) / 128;                 // 391
    node_logits_kernel<<<node_blocks, 128>>>(x, W);

    const int groups = (NUM_EDGES + 7) / 8;                          // 200000
    const int edge_blocks = (groups + 255) / 256;                    // 782
    edge_kernel<<<edge_blocks, 256>>>(ei, et, out);
}

// round 4
// speedup vs baseline: 1.0148x; 1.0043x over previous
#include <cuda_runtime.h>
#include <cstdint>

#define NUM_NODES 50000
#define INPUT_SIZE 128
#define NUM_REL 16
#define NUM_EDGES 1600000
#define CLAMP_MIN 1e-5f
#define CLAMP_MAX 0.99999f

// Node logit table: T[n][0:16] = x[n].W_src, T[n][16:32] = x[n].W_dst
__device__ float g_table[NUM_NODES * 32];

// Packed f32x2 helpers (Blackwell): lanewise fma on 64-bit register pairs.
__device__ __forceinline__ uint64_t pack2(float lo, float hi) {
    uint64_t r;
    asm("mov.b64 %0, {%1, %2};" : "=l"(r) : "f"(lo), "f"(hi));
    return r;
}
__device__ __forceinline__ void fma2(uint64_t& acc, uint64_t a, uint64_t b) {
    asm("fma.rn.f32x2 %0, %1, %2, %0;" : "+l"(acc) : "l"(a), "l"(b));
}
__device__ __forceinline__ float2 unpack2(uint64_t v) {
    float lo, hi;
    asm("mov.b64 {%0, %1}, %2;" : "=f"(lo), "=f"(hi) : "l"(v));
    return make_float2(lo, hi);
}

// ---------------------------------------------------------------------------
// Kernel A: 50000x128 @ 128x32 GEMM into g_table.
// 128 threads/block, tile 128 nodes x 32 cols. Per thread: 8 nodes x 4 cols,
// accumulated as 4 node-pairs x 4 cols in f32x2 packed FFMA.
// W read directly from global (16KB, L1-resident); only Xs staged in smem.
// ---------------------------------------------------------------------------
#define XPAD 132

__global__ void __launch_bounds__(128) node_logits_kernel(
    const float* __restrict__ x, const float* __restrict__ W)
{
    __shared__ float Xs[32][XPAD];     // [k][node], 16.9 KB

    const int tid = threadIdx.x;
    const int node0 = blockIdx.x * 128;
    const int rg = tid & 7;            // 8 groups of 4 rel-cols
    const int ng = tid >> 3;           // 16 groups of 8 nodes

    // Per-thread W base: cols rg*4..rg*4+3 of combined [128][32] layout.
    // rg<4 -> src block rows 0..127, cols rg*4..; rg>=4 -> dst block rows 128..255.
    const float* wp = W + (rg < 4 ? 0 : INPUT_SIZE * NUM_REL) + (rg & 3) * 4;

    uint64_t acc2[4][4];               // [node-pair][col]
#pragma unroll
    for (int i = 0; i < 4; ++i)
#pragma unroll
        for (int j = 0; j < 4; ++j) acc2[i][j] = 0ull;

    for (int kc = 0; kc < 4; ++kc) {
        __syncthreads();
#pragma unroll
        for (int it = 0; it < 8; ++it) {
            int s = tid + it * 128;    // 0..1023
            int row = s >> 3;          // node within tile 0..127
            int c4  = s & 7;           // float4 within 32-float k-chunk
            int gr = node0 + row;
            if (gr >= NUM_NODES) gr = NUM_NODES - 1;
            float4 v = *reinterpret_cast<const float4*>(
                &x[(size_t)gr * INPUT_SIZE + kc * 32 + c4 * 4]);
            Xs[c4 * 4 + 0][row] = v.x;
            Xs[c4 * 4 + 1][row] = v.y;
            Xs[c4 * 4 + 2][row] = v.z;
            Xs[c4 * 4 + 3][row] = v.w;
        }
        __syncthreads();

#pragma unroll
        for (int kk = 0; kk < 32; ++kk) {
            int k = kc * 32 + kk;
            float4 wv = __ldg(reinterpret_cast<const float4*>(wp + (size_t)k * NUM_REL));
            uint64_t wd[4] = { pack2(wv.x, wv.x), pack2(wv.y, wv.y),
                               pack2(wv.z, wv.z), pack2(wv.w, wv.w) };
            float4 xa = *reinterpret_cast<const float4*>(&Xs[kk][ng * 8]);
            float4 xb = *reinterpret_cast<const float4*>(&Xs[kk][ng * 8 + 4]);
            uint64_t xp[4] = { pack2(xa.x, xa.y), pack2(xa.z, xa.w),
                               pack2(xb.x, xb.y), pack2(xb.z, xb.w) };
#pragma unroll
            for (int i = 0; i < 4; ++i)
#pragma unroll
                for (int j = 0; j < 4; ++j)
                    fma2(acc2[i][j], xp[i], wd[j]);
        }
    }

    // acc2[i][j] holds (node ng*8+2i, node ng*8+2i+1) for col rg*4+j.
#pragma unroll
    for (int i = 0; i < 4; ++i) {
        float2 c0 = unpack2(acc2[i][0]);
        float2 c1 = unpack2(acc2[i][1]);
        float2 c2 = unpack2(acc2[i][2]);
        float2 c3 = unpack2(acc2[i][3]);
        int n0 = node0 + ng * 8 + 2 * i;
        if (n0 < NUM_NODES)
            *reinterpret_cast<float4*>(&g_table[(size_t)n0 * 32 + rg * 4]) =
                make_float4(c0.x, c1.x, c2.x, c3.x);
        if (n0 + 1 < NUM_NODES)
            *reinterpret_cast<float4*>(&g_table[(size_t)(n0 + 1) * 32 + rg * 4]) =
                make_float4(c0.y, c1.y, c2.y, c3.y);
    }
}

// ---------------------------------------------------------------------------
// Kernel B: per-edge gather + sigmoid + clamp. 4 edges/thread (best measured
// occupancy/latency balance), coalesced int4/float4 edge traffic.
// ---------------------------------------------------------------------------
__global__ void __launch_bounds__(256) edge_kernel(
    const int* __restrict__ ei,
    const int* __restrict__ et,
    float* __restrict__ out)
{
    const int q = blockIdx.x * 256 + threadIdx.x;
    const int e0 = q * 4;
    if (e0 + 3 < NUM_EDGES) {
        int4 s4 = *reinterpret_cast<const int4*>(ei + e0);
        int4 d4 = *reinterpret_cast<const int4*>(ei + NUM_EDGES + e0);
        int4 t4 = *reinterpret_cast<const int4*>(et + e0);

        float a0 = __ldg(&g_table[s4.x * 32 + t4.x]);
        float a1 = __ldg(&g_table[s4.y * 32 + t4.y]);
        float a2 = __ldg(&g_table[s4.z * 32 + t4.z]);
        float a3 = __ldg(&g_table[s4.w * 32 + t4.w]);
        float b0 = __ldg(&g_table[d4.x * 32 + 16 + t4.x]);
        float b1 = __ldg(&g_table[d4.y * 32 + 16 + t4.y]);
        float b2 = __ldg(&g_table[d4.z * 32 + 16 + t4.z]);
        float b3 = __ldg(&g_table[d4.w * 32 + 16 + t4.w]);

        float4 o;
        o.x = fminf(fmaxf(1.0f / (1.0f + __expf(-(a0 + b0))), CLAMP_MIN), CLAMP_MAX);
        o.y = fminf(fmaxf(1.0f / (1.0f + __expf(-(a1 + b1))), CLAMP_MIN), CLAMP_MAX);
        o.z = fminf(fmaxf(1.0f / (1.0f + __expf(-(a2 + b2))), CLAMP_MIN), CLAMP_MAX);
        o.w = fminf(fmaxf(1.0f / (1.0f + __expf(-(a3 + b3))), CLAMP_MIN), CLAMP_MAX);
        *reinterpret_cast<float4*>(out + e0) = o;
    } else {
        for (int e = e0; e < NUM_EDGES; ++e) {
            int s = ei[e], d = ei[NUM_EDGES + e], t = et[e];
            float p = 1.0f / (1.0f + __expf(-(g_table[s * 32 + t] + g_table[d * 32 + 16 + t])));
            out[e] = fminf(fmaxf(p, CLAMP_MIN), CLAMP_MAX);
        }
    }
}

extern "C" void kernel_launch(void* const* d_in, const int* in_sizes, int n_in,
                              void* d_out, int out_size)
{
    const float* x  = (const float*)d_in[0];
    const float* W  = (const float*)d_in[1];
    const int*   ei = (const int*)d_in[2];
    const int*   et = (const int*)d_in[3];
    float* out = (float*)d_out;

    const int node_blocks = (NUM_NODES + 127) / 128;     // 391
    node_logits_kernel<<<node_blocks, 128>>>(x, W);

    const int quads = (NUM_EDGES + 3) / 4;               // 400000
    const int edge_blocks = (quads + 255) / 256;         // 1563
    edge_kernel<<<edge_blocks, 256>>>(ei, et, out);
}